// round 1
// baseline (speedup 1.0000x reference)
#include <cuda_runtime.h>
#include <math.h>

#define D_MODEL 512
#define N_HEADS 8
#define HEAD_E  64
#define D_FF    2048
#define BATCH   4
#define SEQ     2048
#define M_ROWS  (BATCH*SEQ)   /* 8192 */

// ---------------- scratch (device globals: allocation-guard safe) ----------
__device__ float g_q   [M_ROWS * D_MODEL];
__device__ float g_k   [M_ROWS * D_MODEL];
__device__ float g_v   [M_ROWS * D_MODEL];
__device__ float g_attn[M_ROWS * D_MODEL];
__device__ float g_proj[M_ROWS * D_MODEL];
__device__ float g_x1  [M_ROWS * D_MODEL];
__device__ float g_h   [M_ROWS * D_FF];
__device__ float g_ffn [M_ROWS * D_MODEL];

// ---------------- GEMM: C[M,N] = A[M,K] @ W[K,N] + bias, optional GELU -----
// BM=128, BN=128, BK=8, 256 threads, 8x8 micro-tile per thread.
template<int ACT>
__global__ void __launch_bounds__(256)
gemm_bias_kernel(const float* __restrict__ A, const float* __restrict__ W,
                 const float* __restrict__ bias, float* __restrict__ C,
                 int M, int N, int K)
{
    __shared__ float As[8][128];   // [k][m]
    __shared__ float Bs[8][128];   // [k][n]

    const int tid = threadIdx.x;
    const int tx  = tid & 15;      // n micro-tile
    const int ty  = tid >> 4;      // m micro-tile
    const int m0  = blockIdx.y * 128;
    const int n0  = blockIdx.x * 128;

    float acc[8][8];
    #pragma unroll
    for (int i = 0; i < 8; i++)
        #pragma unroll
        for (int j = 0; j < 8; j++) acc[i][j] = 0.0f;

    const int ar  = tid >> 1;            // A row 0..127
    const int akq = (tid & 1) << 2;      // A k offset 0 or 4
    const int bk  = tid >> 5;            // B k 0..7
    const int bn4 = (tid & 31) << 2;     // B n offset

    for (int k0 = 0; k0 < K; k0 += 8) {
        // A tile: 128x8, coalesced float4, stored transposed [k][m]
        float4 a4 = *(const float4*)&A[(size_t)(m0 + ar) * K + k0 + akq];
        As[akq + 0][ar] = a4.x;
        As[akq + 1][ar] = a4.y;
        As[akq + 2][ar] = a4.z;
        As[akq + 3][ar] = a4.w;
        // B tile: 8x128, coalesced float4, row-major [k][n]
        *(float4*)&Bs[bk][bn4] = *(const float4*)&W[(size_t)(k0 + bk) * N + n0 + bn4];
        __syncthreads();

        #pragma unroll
        for (int kk = 0; kk < 8; kk++) {
            float a[8], b[8];
            *(float4*)&a[0] = *(const float4*)&As[kk][ty * 8];
            *(float4*)&a[4] = *(const float4*)&As[kk][ty * 8 + 4];
            *(float4*)&b[0] = *(const float4*)&Bs[kk][tx * 8];
            *(float4*)&b[4] = *(const float4*)&Bs[kk][tx * 8 + 4];
            #pragma unroll
            for (int i = 0; i < 8; i++)
                #pragma unroll
                for (int j = 0; j < 8; j++)
                    acc[i][j] += a[i] * b[j];
        }
        __syncthreads();
    }

    #pragma unroll
    for (int i = 0; i < 8; i++) {
        const int row = m0 + ty * 8 + i;
        #pragma unroll
        for (int j = 0; j < 8; j += 4) {
            float4 o;
            float* ap = &acc[i][j];
            const int col = n0 + tx * 8 + j;
            o.x = ap[0] + bias[col + 0];
            o.y = ap[1] + bias[col + 1];
            o.z = ap[2] + bias[col + 2];
            o.w = ap[3] + bias[col + 3];
            if (ACT == 1) {  // exact-erf GELU
                o.x = 0.5f * o.x * (1.0f + erff(o.x * 0.70710678118654752f));
                o.y = 0.5f * o.y * (1.0f + erff(o.y * 0.70710678118654752f));
                o.z = 0.5f * o.z * (1.0f + erff(o.z * 0.70710678118654752f));
                o.w = 0.5f * o.w * (1.0f + erff(o.w * 0.70710678118654752f));
            }
            *(float4*)&C[(size_t)row * N + col] = o;
        }
    }
}

// ---------------- flash attention (no mask) --------------------------------
// grid: (SEQ/128, N_HEADS, BATCH), 128 threads; thread = one query row.
// Streams keys in tiles of 32, online softmax, o[64] in registers.
__global__ void __launch_bounds__(128)
attn_kernel(const float* __restrict__ Q, const float* __restrict__ Kk,
            const float* __restrict__ V, float* __restrict__ O)
{
    __shared__ float q_s[64 * 128];  // [e][r]
    __shared__ float k_s[64 * 32];   // [e][j]
    __shared__ float v_s[32 * 64];   // [j][c]

    const int tid = threadIdx.x;
    const int b   = blockIdx.z;
    const int h   = blockIdx.y;
    const int l0  = blockIdx.x * 128;
    const float scale = 0.125f;  // 1/sqrt(64)

    // Load Q tile (128 rows x 64), store transposed [e][r]
    #pragma unroll
    for (int i = 0; i < 16; i++) {
        const int li = tid + i * 128;
        const int r  = li >> 4;
        const int e4 = (li & 15) << 2;
        float4 f = *(const float4*)&Q[((size_t)(b * SEQ + l0 + r)) * D_MODEL + h * HEAD_E + e4];
        q_s[(e4 + 0) * 128 + r] = f.x;
        q_s[(e4 + 1) * 128 + r] = f.y;
        q_s[(e4 + 2) * 128 + r] = f.z;
        q_s[(e4 + 3) * 128 + r] = f.w;
    }
    __syncthreads();

    float o[64];
    #pragma unroll
    for (int c = 0; c < 64; c++) o[c] = 0.0f;
    float m = -1e30f, l = 0.0f;

    for (int s0 = 0; s0 < SEQ; s0 += 32) {
        // Load K tile transposed [e][j] and V tile [j][c]
        #pragma unroll
        for (int i = 0; i < 4; i++) {
            const int li = tid + i * 128;
            const int j  = li >> 4;
            const int e4 = (li & 15) << 2;
            const size_t base = ((size_t)(b * SEQ + s0 + j)) * D_MODEL + h * HEAD_E + e4;
            float4 f = *(const float4*)&Kk[base];
            k_s[(e4 + 0) * 32 + j] = f.x;
            k_s[(e4 + 1) * 32 + j] = f.y;
            k_s[(e4 + 2) * 32 + j] = f.z;
            k_s[(e4 + 3) * 32 + j] = f.w;
            float4 g = *(const float4*)&V[base];
            *(float4*)&v_s[j * 64 + e4] = g;
        }
        __syncthreads();

        // scores s[j] = q_row . k_j
        float s[32];
        #pragma unroll
        for (int j = 0; j < 32; j++) s[j] = 0.0f;
        #pragma unroll 4
        for (int e = 0; e < 64; e++) {
            const float qe = q_s[e * 128 + tid];
            #pragma unroll
            for (int j4 = 0; j4 < 8; j4++) {
                float4 kv = *(const float4*)&k_s[e * 32 + j4 * 4];
                s[j4 * 4 + 0] += qe * kv.x;
                s[j4 * 4 + 1] += qe * kv.y;
                s[j4 * 4 + 2] += qe * kv.z;
                s[j4 * 4 + 3] += qe * kv.w;
            }
        }

        // online softmax
        float mn = m;
        #pragma unroll
        for (int j = 0; j < 32; j++) { s[j] *= scale; mn = fmaxf(mn, s[j]); }
        const float corr = __expf(m - mn);
        l *= corr;
        #pragma unroll
        for (int c = 0; c < 64; c++) o[c] *= corr;
        float ps = 0.0f;
        #pragma unroll
        for (int j = 0; j < 32; j++) { float p = __expf(s[j] - mn); s[j] = p; ps += p; }
        l += ps;
        m = mn;

        // o += p @ V
        #pragma unroll
        for (int j = 0; j < 32; j++) {
            const float p = s[j];
            #pragma unroll
            for (int c4 = 0; c4 < 16; c4++) {
                float4 vv = *(const float4*)&v_s[j * 64 + c4 * 4];
                o[c4 * 4 + 0] += p * vv.x;
                o[c4 * 4 + 1] += p * vv.y;
                o[c4 * 4 + 2] += p * vv.z;
                o[c4 * 4 + 3] += p * vv.w;
            }
        }
        __syncthreads();
    }

    const float inv = 1.0f / l;
    #pragma unroll
    for (int c4 = 0; c4 < 16; c4++) {
        float4 w;
        w.x = o[c4 * 4 + 0] * inv;
        w.y = o[c4 * 4 + 1] * inv;
        w.z = o[c4 * 4 + 2] * inv;
        w.w = o[c4 * 4 + 3] * inv;
        *(float4*)&O[((size_t)(b * SEQ + l0 + tid)) * D_MODEL + h * HEAD_E + c4 * 4] = w;
    }
}

// ---------------- residual add + LayerNorm ---------------------------------
// one CTA per row of 512; 128 threads, float4 each.
__global__ void __launch_bounds__(128)
add_ln_kernel(const float* __restrict__ X, const float* __restrict__ Y,
              const float* __restrict__ g, const float* __restrict__ bta,
              float* __restrict__ Out)
{
    __shared__ float red[8];
    const int row = blockIdx.x;
    const int tid = threadIdx.x;
    const int col = tid * 4;

    float4 xv = *(const float4*)&X[(size_t)row * D_MODEL + col];
    float4 yv = *(const float4*)&Y[(size_t)row * D_MODEL + col];
    float v0 = xv.x + yv.x, v1 = xv.y + yv.y, v2 = xv.z + yv.z, v3 = xv.w + yv.w;

    float sum = v0 + v1 + v2 + v3;
    float sq  = v0 * v0 + v1 * v1 + v2 * v2 + v3 * v3;
    #pragma unroll
    for (int off = 16; off > 0; off >>= 1) {
        sum += __shfl_xor_sync(0xFFFFFFFFu, sum, off);
        sq  += __shfl_xor_sync(0xFFFFFFFFu, sq,  off);
    }
    const int wid  = tid >> 5;
    const int lane = tid & 31;
    if (lane == 0) { red[wid] = sum; red[4 + wid] = sq; }
    __syncthreads();
    sum = red[0] + red[1] + red[2] + red[3];
    sq  = red[4] + red[5] + red[6] + red[7];

    const float mu  = sum * (1.0f / D_MODEL);
    const float var = sq * (1.0f / D_MODEL) - mu * mu;
    const float rst = rsqrtf(var + 1e-5f);

    float4 gv = *(const float4*)&g[col];
    float4 bv = *(const float4*)&bta[col];
    float4 w;
    w.x = (v0 - mu) * rst * gv.x + bv.x;
    w.y = (v1 - mu) * rst * gv.y + bv.y;
    w.z = (v2 - mu) * rst * gv.z + bv.z;
    w.w = (v3 - mu) * rst * gv.w + bv.w;
    *(float4*)&Out[(size_t)row * D_MODEL + col] = w;
}

// ---------------- launcher --------------------------------------------------
extern "C" void kernel_launch(void* const* d_in, const int* in_sizes, int n_in,
                              void* d_out, int out_size)
{
    const float* x   = (const float*)d_in[0];
    const float* Wq  = (const float*)d_in[1];
    const float* bq  = (const float*)d_in[2];
    const float* Wk  = (const float*)d_in[3];
    const float* bk  = (const float*)d_in[4];
    const float* Wv  = (const float*)d_in[5];
    const float* bv  = (const float*)d_in[6];
    const float* Wo  = (const float*)d_in[7];
    const float* bo  = (const float*)d_in[8];
    const float* W1  = (const float*)d_in[9];
    const float* b1  = (const float*)d_in[10];
    const float* W2  = (const float*)d_in[11];
    const float* b2  = (const float*)d_in[12];
    const float* g1  = (const float*)d_in[13];
    const float* be1 = (const float*)d_in[14];
    const float* g2  = (const float*)d_in[15];
    const float* be2 = (const float*)d_in[16];
    float* out = (float*)d_out;

    float *q, *k, *v, *attn, *proj, *x1, *hbuf, *ffn;
    cudaGetSymbolAddress((void**)&q,    g_q);
    cudaGetSymbolAddress((void**)&k,    g_k);
    cudaGetSymbolAddress((void**)&v,    g_v);
    cudaGetSymbolAddress((void**)&attn, g_attn);
    cudaGetSymbolAddress((void**)&proj, g_proj);
    cudaGetSymbolAddress((void**)&x1,   g_x1);
    cudaGetSymbolAddress((void**)&hbuf, g_h);
    cudaGetSymbolAddress((void**)&ffn,  g_ffn);

    const dim3 gD(D_MODEL / 128, M_ROWS / 128);   // (4, 64)
    const dim3 gF(D_FF   / 128, M_ROWS / 128);    // (16, 64)

    // QKV projections
    gemm_bias_kernel<0><<<gD, 256>>>(x, Wq, bq, q, M_ROWS, D_MODEL, D_MODEL);
    gemm_bias_kernel<0><<<gD, 256>>>(x, Wk, bk, k, M_ROWS, D_MODEL, D_MODEL);
    gemm_bias_kernel<0><<<gD, 256>>>(x, Wv, bv, v, M_ROWS, D_MODEL, D_MODEL);

    // attention
    attn_kernel<<<dim3(SEQ / 128, N_HEADS, BATCH), 128>>>(q, k, v, attn);

    // output projection + residual LN1
    gemm_bias_kernel<0><<<gD, 256>>>(attn, Wo, bo, proj, M_ROWS, D_MODEL, D_MODEL);
    add_ln_kernel<<<M_ROWS, 128>>>(x, proj, g1, be1, x1);

    // FFN + residual LN2
    gemm_bias_kernel<1><<<gF, 256>>>(x1, W1, b1, hbuf, M_ROWS, D_FF, D_MODEL);
    gemm_bias_kernel<0><<<gD, 256>>>(hbuf, W2, b2, ffn, M_ROWS, D_MODEL, D_FF);
    add_ln_kernel<<<M_ROWS, 128>>>(x1, ffn, g2, be2, out);
}

// round 2
// speedup vs baseline: 2.6966x; 2.6966x over previous
#include <cuda_runtime.h>
#include <math.h>

#define D_MODEL 512
#define N_HEADS 8
#define HEAD_E  64
#define D_FF    2048
#define BATCH   4
#define SEQ     2048
#define M_ROWS  (BATCH*SEQ)   /* 8192 */
#define LLSZ    ((size_t)SEQ*(size_t)SEQ)

// ---------------- scratch (device globals: allocation-guard safe) ----------
__device__ float g_q   [M_ROWS * D_MODEL];
__device__ float g_k   [M_ROWS * D_MODEL];
__device__ float g_v   [M_ROWS * D_MODEL];
__device__ float g_attn[M_ROWS * D_MODEL];
__device__ float g_proj[M_ROWS * D_MODEL];
__device__ float g_x1  [M_ROWS * D_MODEL];
__device__ float g_h   [M_ROWS * D_FF];
__device__ float g_ffn [M_ROWS * D_MODEL];
__device__ float g_scores[(size_t)BATCH * N_HEADS * LLSZ];  // 537 MB
__device__ float g_zero[D_FF];  // zero-initialized (no-bias GEMMs)

// ---------------- tf32 helpers ---------------------------------------------
__device__ __forceinline__ unsigned f2tf(float f) {
    unsigned u;
    asm("cvt.rna.tf32.f32 %0, %1;" : "=r"(u) : "f"(f));
    return u;
}

__device__ __forceinline__ void mma8(float* c, const unsigned* a, const unsigned* b) {
    asm volatile(
        "mma.sync.aligned.m16n8k8.row.col.f32.tf32.tf32.f32 "
        "{%0,%1,%2,%3},{%4,%5,%6,%7},{%8,%9},{%0,%1,%2,%3};"
        : "+f"(c[0]), "+f"(c[1]), "+f"(c[2]), "+f"(c[3])
        : "r"(a[0]), "r"(a[1]), "r"(a[2]), "r"(a[3]), "r"(b[0]), "r"(b[1]));
}

__device__ __forceinline__ float gelu_exact(float v) {
    return 0.5f * v * (1.0f + erff(v * 0.70710678118654752f));
}

// ---------------- tf32 tensor-core GEMM ------------------------------------
// C[M,N] = A[M,K] @ op(B) + bias  (op = transpose if TRB: B stored [N,K])
// BM=128, BK=32, 256 threads = 8 warps (4 m x 2 n), warp tile 32 x (BN/2).
// Batched over blockIdx.z via (stride_b, stride_h) pairs: off = b*sb + h*sh,
// with b = z>>3, h = z&7.
template<int BN, int ACT, bool TRB>
__global__ void __launch_bounds__(256)
mma_gemm(const float* __restrict__ A, const float* __restrict__ B,
         const float* __restrict__ bias, float* __restrict__ C,
         int K, int lda, int ldb, int ldc,
         size_t asb, size_t ash, size_t bsb, size_t bsh,
         size_t csb, size_t csh)
{
    constexpr int BM = 128, BK = 32;
    constexpr int NT_N = BN / 16;               // 8x8 n-tiles per warp

    __shared__ unsigned A_s[BM][BK + 4];        // [m][k], stride 36
    __shared__ unsigned B_s[TRB ? BN : BK][TRB ? (BK + 4) : (BN + 8)];

    const int tid  = threadIdx.x;
    const int warp = tid >> 5, lane = tid & 31;
    const int wm   = warp >> 1, wn = warp & 1;
    const int lr   = lane >> 2, lc = lane & 3;

    const int z  = blockIdx.z;
    const int bz = z >> 3, hz = z & 7;
    A += (size_t)bz * asb + (size_t)hz * ash;
    B += (size_t)bz * bsb + (size_t)hz * bsh;
    C += (size_t)bz * csb + (size_t)hz * csh;

    const int m0 = blockIdx.y * BM;
    const int n0 = blockIdx.x * BN;

    float acc[2][NT_N][4];
    #pragma unroll
    for (int i = 0; i < 2; i++)
        #pragma unroll
        for (int j = 0; j < NT_N; j++)
            #pragma unroll
            for (int r = 0; r < 4; r++) acc[i][j][r] = 0.0f;

    for (int k0 = 0; k0 < K; k0 += BK) {
        // --- A tile: 128x32, coalesced float4, tf32-convert on store ---
        #pragma unroll
        for (int it = 0; it < 4; it++) {
            const int f  = tid + it * 256;
            const int m  = f >> 3;
            const int kq = (f & 7) << 2;
            float4 v = *(const float4*)&A[(size_t)(m0 + m) * lda + k0 + kq];
            A_s[m][kq + 0] = f2tf(v.x);
            A_s[m][kq + 1] = f2tf(v.y);
            A_s[m][kq + 2] = f2tf(v.z);
            A_s[m][kq + 3] = f2tf(v.w);
        }
        // --- B tile ---
        if (TRB) {
            #pragma unroll
            for (int it = 0; it < BN / 32; it++) {
                const int f  = tid + it * 256;
                const int n  = f >> 3;
                const int kq = (f & 7) << 2;
                float4 v = *(const float4*)&B[(size_t)(n0 + n) * ldb + k0 + kq];
                B_s[n][kq + 0] = f2tf(v.x);
                B_s[n][kq + 1] = f2tf(v.y);
                B_s[n][kq + 2] = f2tf(v.z);
                B_s[n][kq + 3] = f2tf(v.w);
            }
        } else {
            #pragma unroll
            for (int it = 0; it < BN / 32; it++) {
                const int f  = tid + it * 256;
                const int kk = f / (BN / 4);
                const int n4 = (f % (BN / 4)) << 2;
                float4 v = *(const float4*)&B[(size_t)(k0 + kk) * ldb + n0 + n4];
                B_s[kk][n4 + 0] = f2tf(v.x);
                B_s[kk][n4 + 1] = f2tf(v.y);
                B_s[kk][n4 + 2] = f2tf(v.z);
                B_s[kk][n4 + 3] = f2tf(v.w);
            }
        }
        __syncthreads();

        #pragma unroll
        for (int ks = 0; ks < 4; ks++) {
            unsigned af[2][4];
            #pragma unroll
            for (int tm = 0; tm < 2; tm++) {
                const int rb = wm * 32 + tm * 16 + lr;
                af[tm][0] = A_s[rb][ks * 8 + lc];
                af[tm][1] = A_s[rb + 8][ks * 8 + lc];
                af[tm][2] = A_s[rb][ks * 8 + 4 + lc];
                af[tm][3] = A_s[rb + 8][ks * 8 + 4 + lc];
            }
            #pragma unroll
            for (int tn = 0; tn < NT_N; tn++) {
                const int cb = wn * (BN / 2) + tn * 8 + lr;
                unsigned bf[2];
                if (TRB) {
                    bf[0] = B_s[cb][ks * 8 + lc];
                    bf[1] = B_s[cb][ks * 8 + 4 + lc];
                } else {
                    bf[0] = B_s[ks * 8 + lc][cb];
                    bf[1] = B_s[ks * 8 + 4 + lc][cb];
                }
                mma8(acc[0][tn], af[0], bf);
                mma8(acc[1][tn], af[1], bf);
            }
        }
        __syncthreads();
    }

    // --- epilogue: bias (+GELU), float2 stores -----------------------------
    #pragma unroll
    for (int tm = 0; tm < 2; tm++) {
        #pragma unroll
        for (int tn = 0; tn < NT_N; tn++) {
            const int row = m0 + wm * 32 + tm * 16 + lr;
            const int col = n0 + wn * (BN / 2) + tn * 8 + 2 * lc;
            const float b0 = bias[col], b1 = bias[col + 1];
            float2 v0 = make_float2(acc[tm][tn][0] + b0, acc[tm][tn][1] + b1);
            float2 v1 = make_float2(acc[tm][tn][2] + b0, acc[tm][tn][3] + b1);
            if (ACT) {
                v0.x = gelu_exact(v0.x); v0.y = gelu_exact(v0.y);
                v1.x = gelu_exact(v1.x); v1.y = gelu_exact(v1.y);
            }
            *(float2*)&C[(size_t)row * ldc + col]       = v0;
            *(float2*)&C[(size_t)(row + 8) * ldc + col] = v1;
        }
    }
}

// ---------------- row softmax over SEQ=2048, scale folded ------------------
__global__ void __launch_bounds__(256)
softmax_kernel(float* __restrict__ S)
{
    __shared__ float red[8];
    float* p = S + (size_t)blockIdx.x * SEQ;
    const int tid  = threadIdx.x;
    const int warp = tid >> 5, lane = tid & 31;

    float4 a = *(float4*)(p + tid * 8);
    float4 b = *(float4*)(p + tid * 8 + 4);

    float mx = fmaxf(fmaxf(fmaxf(a.x, a.y), fmaxf(a.z, a.w)),
                     fmaxf(fmaxf(b.x, b.y), fmaxf(b.z, b.w)));
    #pragma unroll
    for (int off = 16; off > 0; off >>= 1)
        mx = fmaxf(mx, __shfl_xor_sync(0xFFFFFFFFu, mx, off));
    if (lane == 0) red[warp] = mx;
    __syncthreads();
    float m2 = red[0];
    #pragma unroll
    for (int i = 1; i < 8; i++) m2 = fmaxf(m2, red[i]);
    __syncthreads();

    const float sc = 0.125f;  // 1/sqrt(64)
    a.x = __expf((a.x - m2) * sc); a.y = __expf((a.y - m2) * sc);
    a.z = __expf((a.z - m2) * sc); a.w = __expf((a.w - m2) * sc);
    b.x = __expf((b.x - m2) * sc); b.y = __expf((b.y - m2) * sc);
    b.z = __expf((b.z - m2) * sc); b.w = __expf((b.w - m2) * sc);

    float sm = a.x + a.y + a.z + a.w + b.x + b.y + b.z + b.w;
    #pragma unroll
    for (int off = 16; off > 0; off >>= 1)
        sm += __shfl_xor_sync(0xFFFFFFFFu, sm, off);
    if (lane == 0) red[warp] = sm;
    __syncthreads();
    float tot = red[0] + red[1] + red[2] + red[3]
              + red[4] + red[5] + red[6] + red[7];
    const float inv = 1.0f / tot;

    a.x *= inv; a.y *= inv; a.z *= inv; a.w *= inv;
    b.x *= inv; b.y *= inv; b.z *= inv; b.w *= inv;
    *(float4*)(p + tid * 8)     = a;
    *(float4*)(p + tid * 8 + 4) = b;
}

// ---------------- residual add + LayerNorm ---------------------------------
__global__ void __launch_bounds__(128)
add_ln_kernel(const float* __restrict__ X, const float* __restrict__ Y,
              const float* __restrict__ g, const float* __restrict__ bta,
              float* __restrict__ Out)
{
    __shared__ float red[8];
    const int row = blockIdx.x;
    const int tid = threadIdx.x;
    const int col = tid * 4;

    float4 xv = *(const float4*)&X[(size_t)row * D_MODEL + col];
    float4 yv = *(const float4*)&Y[(size_t)row * D_MODEL + col];
    float v0 = xv.x + yv.x, v1 = xv.y + yv.y, v2 = xv.z + yv.z, v3 = xv.w + yv.w;

    float sum = v0 + v1 + v2 + v3;
    float sq  = v0 * v0 + v1 * v1 + v2 * v2 + v3 * v3;
    #pragma unroll
    for (int off = 16; off > 0; off >>= 1) {
        sum += __shfl_xor_sync(0xFFFFFFFFu, sum, off);
        sq  += __shfl_xor_sync(0xFFFFFFFFu, sq,  off);
    }
    const int wid  = tid >> 5;
    const int lane = tid & 31;
    if (lane == 0) { red[wid] = sum; red[4 + wid] = sq; }
    __syncthreads();
    sum = red[0] + red[1] + red[2] + red[3];
    sq  = red[4] + red[5] + red[6] + red[7];

    const float mu  = sum * (1.0f / D_MODEL);
    const float var = sq * (1.0f / D_MODEL) - mu * mu;
    const float rst = rsqrtf(var + 1e-5f);

    float4 gv = *(const float4*)&g[col];
    float4 bv = *(const float4*)&bta[col];
    float4 w;
    w.x = (v0 - mu) * rst * gv.x + bv.x;
    w.y = (v1 - mu) * rst * gv.y + bv.y;
    w.z = (v2 - mu) * rst * gv.z + bv.z;
    w.w = (v3 - mu) * rst * gv.w + bv.w;
    *(float4*)&Out[(size_t)row * D_MODEL + col] = w;
}

// ---------------- launcher --------------------------------------------------
extern "C" void kernel_launch(void* const* d_in, const int* in_sizes, int n_in,
                              void* d_out, int out_size)
{
    const float* x   = (const float*)d_in[0];
    const float* Wq  = (const float*)d_in[1];
    const float* bq  = (const float*)d_in[2];
    const float* Wk  = (const float*)d_in[3];
    const float* bk  = (const float*)d_in[4];
    const float* Wv  = (const float*)d_in[5];
    const float* bv  = (const float*)d_in[6];
    const float* Wo  = (const float*)d_in[7];
    const float* bo  = (const float*)d_in[8];
    const float* W1  = (const float*)d_in[9];
    const float* b1  = (const float*)d_in[10];
    const float* W2  = (const float*)d_in[11];
    const float* b2  = (const float*)d_in[12];
    const float* g1  = (const float*)d_in[13];
    const float* be1 = (const float*)d_in[14];
    const float* g2  = (const float*)d_in[15];
    const float* be2 = (const float*)d_in[16];
    float* out = (float*)d_out;

    float *q, *k, *v, *attn, *proj, *x1, *hbuf, *ffn, *scr, *zb;
    cudaGetSymbolAddress((void**)&q,    g_q);
    cudaGetSymbolAddress((void**)&k,    g_k);
    cudaGetSymbolAddress((void**)&v,    g_v);
    cudaGetSymbolAddress((void**)&attn, g_attn);
    cudaGetSymbolAddress((void**)&proj, g_proj);
    cudaGetSymbolAddress((void**)&x1,   g_x1);
    cudaGetSymbolAddress((void**)&hbuf, g_h);
    cudaGetSymbolAddress((void**)&ffn,  g_ffn);
    cudaGetSymbolAddress((void**)&scr,  g_scores);
    cudaGetSymbolAddress((void**)&zb,   g_zero);

    const size_t sBH = (size_t)SEQ * D_MODEL;   // per-batch stride in q/k/v
    const dim3 gD(D_MODEL / 128, M_ROWS / 128);   // (4, 64)
    const dim3 gF(D_FF   / 128, M_ROWS / 128);    // (16, 64)

    // QKV projections: C = x @ W + b
    mma_gemm<128,0,false><<<gD, 256>>>(x, Wq, bq, q, D_MODEL, D_MODEL, D_MODEL, D_MODEL, 0,0,0,0,0,0);
    mma_gemm<128,0,false><<<gD, 256>>>(x, Wk, bk, k, D_MODEL, D_MODEL, D_MODEL, D_MODEL, 0,0,0,0,0,0);
    mma_gemm<128,0,false><<<gD, 256>>>(x, Wv, bv, v, D_MODEL, D_MODEL, D_MODEL, D_MODEL, 0,0,0,0,0,0);

    // scores[z, l, s] = Q_z[l,:] . K_z[s,:]   (batched NT GEMM, z = b*8+h)
    mma_gemm<128,0,true><<<dim3(SEQ/128, SEQ/128, BATCH*N_HEADS), 256>>>(
        q, k, zb, scr, HEAD_E, D_MODEL, D_MODEL, SEQ,
        sBH, HEAD_E, sBH, HEAD_E, (size_t)N_HEADS * LLSZ, LLSZ);

    // softmax rows (scale 1/8 folded)
    softmax_kernel<<<BATCH * N_HEADS * SEQ, 256>>>(scr);

    // attn[b,l,h,:] = P_z @ V_z   (batched NN GEMM, N=64)
    mma_gemm<64,0,false><<<dim3(1, SEQ/128, BATCH*N_HEADS), 256>>>(
        scr, v, zb, attn, SEQ, SEQ, D_MODEL, D_MODEL,
        (size_t)N_HEADS * LLSZ, LLSZ, sBH, HEAD_E, sBH, HEAD_E);

    // output projection + residual LN1
    mma_gemm<128,0,false><<<gD, 256>>>(attn, Wo, bo, proj, D_MODEL, D_MODEL, D_MODEL, D_MODEL, 0,0,0,0,0,0);
    add_ln_kernel<<<M_ROWS, 128>>>(x, proj, g1, be1, x1);

    // FFN (GELU fused in first GEMM) + residual LN2
    mma_gemm<128,1,false><<<gF, 256>>>(x1, W1, b1, hbuf, D_MODEL, D_MODEL, D_FF, D_FF, 0,0,0,0,0,0);
    mma_gemm<128,0,false><<<gD, 256>>>(hbuf, W2, b2, ffn, D_FF, D_FF, D_MODEL, D_MODEL, 0,0,0,0,0,0);
    add_ln_kernel<<<M_ROWS, 128>>>(x1, ffn, g2, be2, out);
}

// round 3
// speedup vs baseline: 3.4330x; 1.2731x over previous
#include <cuda_runtime.h>
#include <math.h>

#define D_MODEL 512
#define N_HEADS 8
#define HEAD_E  64
#define D_FF    2048
#define BATCH   4
#define SEQ     2048
#define M_ROWS  (BATCH*SEQ)   /* 8192 */

// ---------------- scratch (device globals: allocation-guard safe) ----------
__device__ float g_q   [M_ROWS * D_MODEL];
__device__ float g_k   [M_ROWS * D_MODEL];
__device__ float g_v   [M_ROWS * D_MODEL];
__device__ float g_attn[M_ROWS * D_MODEL];
__device__ float g_proj[M_ROWS * D_MODEL];
__device__ float g_x1  [M_ROWS * D_MODEL];
__device__ float g_h   [M_ROWS * D_FF];
__device__ float g_ffn [M_ROWS * D_MODEL];

// ---------------- tf32 helpers ---------------------------------------------
__device__ __forceinline__ unsigned f2tf(float f) {
    unsigned u;
    asm("cvt.rna.tf32.f32 %0, %1;" : "=r"(u) : "f"(f));
    return u;
}

__device__ __forceinline__ void mma8(float* c, const unsigned* a, const unsigned* b) {
    asm volatile(
        "mma.sync.aligned.m16n8k8.row.col.f32.tf32.tf32.f32 "
        "{%0,%1,%2,%3},{%4,%5,%6,%7},{%8,%9},{%0,%1,%2,%3};"
        : "+f"(c[0]), "+f"(c[1]), "+f"(c[2]), "+f"(c[3])
        : "r"(a[0]), "r"(a[1]), "r"(a[2]), "r"(a[3]), "r"(b[0]), "r"(b[1]));
}

__device__ __forceinline__ float gelu_exact(float v) {
    return 0.5f * v * (1.0f + erff(v * 0.70710678118654752f));
}

__device__ __forceinline__ unsigned fbits(float f) { return __float_as_uint(f); }

// ---------------- tf32 GEMM, double-buffered --------------------------------
// C[M,N] = A[M,K] @ B[K,N] + bias (optional exact GELU).
// BM=128, BN=128, BK=16, 256 threads = 8 warps (4m x 2n), warp tile 32x64.
// Register-prefetch double buffering: one barrier per K-tile.
template<int ACT>
__global__ void __launch_bounds__(256)
mma_gemm(const float* __restrict__ A, const float* __restrict__ B,
         const float* __restrict__ bias, float* __restrict__ C,
         int K, int N)
{
    __shared__ unsigned A_s[2][128][20];   // [buf][m][k], pad 4
    __shared__ unsigned B_s[2][16][136];   // [buf][k][n], pad 8

    const int tid  = threadIdx.x;
    const int warp = tid >> 5, lane = tid & 31;
    const int wm   = warp >> 1, wn = warp & 1;
    const int lr   = lane >> 2, lc = lane & 3;
    const int m0   = blockIdx.y * 128;
    const int n0   = blockIdx.x * 128;

    const int am  = tid >> 2;            // A row (it adds +64)
    const int akq = (tid & 3) << 2;      // A k offset
    const int bk  = tid >> 5;            // B k (it adds +8)
    const int bn4 = (tid & 31) << 2;     // B n offset

    float acc[2][8][4];
    #pragma unroll
    for (int i = 0; i < 2; i++)
        #pragma unroll
        for (int j = 0; j < 8; j++)
            #pragma unroll
            for (int r = 0; r < 4; r++) acc[i][j][r] = 0.0f;

    // prologue loads
    float4 aR0 = *(const float4*)&A[(size_t)(m0 + am) * K + akq];
    float4 aR1 = *(const float4*)&A[(size_t)(m0 + am + 64) * K + akq];
    float4 bR0 = *(const float4*)&B[(size_t)bk * N + n0 + bn4];
    float4 bR1 = *(const float4*)&B[(size_t)(bk + 8) * N + n0 + bn4];

    const int KT = K >> 4;
    for (int kt = 0; kt < KT; kt++) {
        const int buf = kt & 1;
        // store current regs -> smem (tf32 convert)
        *(uint4*)&A_s[buf][am][akq] =
            make_uint4(f2tf(aR0.x), f2tf(aR0.y), f2tf(aR0.z), f2tf(aR0.w));
        *(uint4*)&A_s[buf][am + 64][akq] =
            make_uint4(f2tf(aR1.x), f2tf(aR1.y), f2tf(aR1.z), f2tf(aR1.w));
        *(uint4*)&B_s[buf][bk][bn4] =
            make_uint4(f2tf(bR0.x), f2tf(bR0.y), f2tf(bR0.z), f2tf(bR0.w));
        *(uint4*)&B_s[buf][bk + 8][bn4] =
            make_uint4(f2tf(bR1.x), f2tf(bR1.y), f2tf(bR1.z), f2tf(bR1.w));
        __syncthreads();

        // prefetch next tile (overlaps with mma below)
        if (kt + 1 < KT) {
            const int k0 = (kt + 1) << 4;
            aR0 = *(const float4*)&A[(size_t)(m0 + am) * K + k0 + akq];
            aR1 = *(const float4*)&A[(size_t)(m0 + am + 64) * K + k0 + akq];
            bR0 = *(const float4*)&B[(size_t)(k0 + bk) * N + n0 + bn4];
            bR1 = *(const float4*)&B[(size_t)(k0 + bk + 8) * N + n0 + bn4];
        }

        #pragma unroll
        for (int ks = 0; ks < 2; ks++) {
            unsigned af[2][4];
            #pragma unroll
            for (int tm = 0; tm < 2; tm++) {
                const int rb = wm * 32 + tm * 16 + lr;
                af[tm][0] = A_s[buf][rb][ks * 8 + lc];
                af[tm][1] = A_s[buf][rb + 8][ks * 8 + lc];
                af[tm][2] = A_s[buf][rb][ks * 8 + 4 + lc];
                af[tm][3] = A_s[buf][rb + 8][ks * 8 + 4 + lc];
            }
            #pragma unroll
            for (int tn = 0; tn < 8; tn++) {
                const int cb = wn * 64 + tn * 8 + lr;
                unsigned bf[2];
                bf[0] = B_s[buf][ks * 8 + lc][cb];
                bf[1] = B_s[buf][ks * 8 + 4 + lc][cb];
                mma8(acc[0][tn], af[0], bf);
                mma8(acc[1][tn], af[1], bf);
            }
        }
    }

    // epilogue
    #pragma unroll
    for (int tm = 0; tm < 2; tm++) {
        #pragma unroll
        for (int tn = 0; tn < 8; tn++) {
            const int row = m0 + wm * 32 + tm * 16 + lr;
            const int col = n0 + wn * 64 + tn * 8 + 2 * lc;
            const float b0 = bias[col], b1 = bias[col + 1];
            float2 v0 = make_float2(acc[tm][tn][0] + b0, acc[tm][tn][1] + b1);
            float2 v1 = make_float2(acc[tm][tn][2] + b0, acc[tm][tn][3] + b1);
            if (ACT) {
                v0.x = gelu_exact(v0.x); v0.y = gelu_exact(v0.y);
                v1.x = gelu_exact(v1.x); v1.y = gelu_exact(v1.y);
            }
            *(float2*)&C[(size_t)row * N + col]       = v0;
            *(float2*)&C[(size_t)(row + 8) * N + col] = v1;
        }
    }
}

// ---------------- fused flash attention (tf32 tensor cores) ----------------
// grid (SEQ/128, B*H), 256 threads = 8 warps; warp owns 16 query rows.
// Streams K/V in tiles of 64, online softmax on mma C-fragments.
__global__ void __launch_bounds__(256)
flash_kernel(const float* __restrict__ Q, const float* __restrict__ Kg,
             const float* __restrict__ Vg, float* __restrict__ O)
{
    extern __shared__ float sm[];
    float* K_s = sm;                 // [64][68] tf32 bits
    float* V_s = K_s + 64 * 68;      // [64][72] tf32 bits
    float* P_s = V_s + 64 * 72;      // [8][16][68] per-warp P; Q staging at start

    const int tid  = threadIdx.x;
    const int warp = tid >> 5, lane = tid & 31;
    const int lr   = lane >> 2, lc = lane & 3;
    const int bh   = blockIdx.y;
    const int b    = bh >> 3, h = bh & 7;
    const int l0   = blockIdx.x * 128;

    const float* Qb = Q  + ((size_t)(b * SEQ + l0)) * D_MODEL + h * HEAD_E;
    const float* Kb = Kg + ((size_t)(b * SEQ)) * D_MODEL + h * HEAD_E;
    const float* Vb = Vg + ((size_t)(b * SEQ)) * D_MODEL + h * HEAD_E;

    // --- stage Q tile (128x64) into P_s area, extract fragments to regs ----
    #pragma unroll
    for (int it = 0; it < 8; it++) {
        const int f  = tid + it * 256;
        const int r  = f >> 4;
        const int e4 = (f & 15) << 2;
        float4 v = *(const float4*)&Qb[(size_t)r * D_MODEL + e4];
        float* d = &P_s[r * 68 + e4];
        d[0] = v.x; d[1] = v.y; d[2] = v.z; d[3] = v.w;
    }
    __syncthreads();
    unsigned qf[8][4];
    {
        const float* qr  = &P_s[(warp * 16 + lr) * 68];
        const float* qr8 = &P_s[(warp * 16 + lr + 8) * 68];
        #pragma unroll
        for (int ks = 0; ks < 8; ks++) {
            qf[ks][0] = f2tf(qr [ks * 8 + lc]);
            qf[ks][1] = f2tf(qr8[ks * 8 + lc]);
            qf[ks][2] = f2tf(qr [ks * 8 + 4 + lc]);
            qf[ks][3] = f2tf(qr8[ks * 8 + 4 + lc]);
        }
    }
    __syncthreads();

    float oacc[8][4];
    #pragma unroll
    for (int t = 0; t < 8; t++)
        #pragma unroll
        for (int r = 0; r < 4; r++) oacc[t][r] = 0.0f;
    float m0 = -1e30f, m1 = -1e30f, l0s = 0.0f, l1s = 0.0f;

    for (int s0 = 0; s0 < SEQ; s0 += 64) {
        // --- load K,V tiles (64x64), tf32-convert ---
        #pragma unroll
        for (int it = 0; it < 4; it++) {
            const int f  = tid + it * 256;
            const int j  = f >> 4;
            const int e4 = (f & 15) << 2;
            const size_t go = (size_t)(s0 + j) * D_MODEL + e4;
            float4 kv = *(const float4*)&Kb[go];
            unsigned* kd = (unsigned*)&K_s[j * 68 + e4];
            kd[0] = f2tf(kv.x); kd[1] = f2tf(kv.y);
            kd[2] = f2tf(kv.z); kd[3] = f2tf(kv.w);
            float4 vv = *(const float4*)&Vb[go];
            unsigned* vd = (unsigned*)&V_s[j * 72 + e4];
            vd[0] = f2tf(vv.x); vd[1] = f2tf(vv.y);
            vd[2] = f2tf(vv.z); vd[3] = f2tf(vv.w);
        }
        __syncthreads();

        // --- S = Q @ K^T (warp: 16x64) ---
        float sacc[8][4];
        #pragma unroll
        for (int t = 0; t < 8; t++)
            #pragma unroll
            for (int r = 0; r < 4; r++) sacc[t][r] = 0.0f;
        #pragma unroll
        for (int ks = 0; ks < 8; ks++) {
            #pragma unroll
            for (int tn = 0; tn < 8; tn++) {
                const int cb = tn * 8 + lr;
                unsigned bf[2];
                bf[0] = fbits(K_s[cb * 68 + ks * 8 + lc]);
                bf[1] = fbits(K_s[cb * 68 + ks * 8 + 4 + lc]);
                mma8(sacc[tn], qf[ks], bf);
            }
        }

        // --- online softmax (rows lr and lr+8) ---
        const float sc = 0.125f;
        float mx0 = -1e30f, mx1 = -1e30f;
        #pragma unroll
        for (int tn = 0; tn < 8; tn++) {
            sacc[tn][0] *= sc; sacc[tn][1] *= sc;
            sacc[tn][2] *= sc; sacc[tn][3] *= sc;
            mx0 = fmaxf(mx0, fmaxf(sacc[tn][0], sacc[tn][1]));
            mx1 = fmaxf(mx1, fmaxf(sacc[tn][2], sacc[tn][3]));
        }
        mx0 = fmaxf(mx0, __shfl_xor_sync(0xFFFFFFFFu, mx0, 1));
        mx0 = fmaxf(mx0, __shfl_xor_sync(0xFFFFFFFFu, mx0, 2));
        mx1 = fmaxf(mx1, __shfl_xor_sync(0xFFFFFFFFu, mx1, 1));
        mx1 = fmaxf(mx1, __shfl_xor_sync(0xFFFFFFFFu, mx1, 2));
        const float nm0 = fmaxf(m0, mx0), nm1 = fmaxf(m1, mx1);
        const float c0 = __expf(m0 - nm0), c1 = __expf(m1 - nm1);
        m0 = nm0; m1 = nm1;

        float ps0 = 0.0f, ps1 = 0.0f;
        #pragma unroll
        for (int tn = 0; tn < 8; tn++) {
            float p;
            p = __expf(sacc[tn][0] - nm0); sacc[tn][0] = p; ps0 += p;
            p = __expf(sacc[tn][1] - nm0); sacc[tn][1] = p; ps0 += p;
            p = __expf(sacc[tn][2] - nm1); sacc[tn][2] = p; ps1 += p;
            p = __expf(sacc[tn][3] - nm1); sacc[tn][3] = p; ps1 += p;
        }
        ps0 += __shfl_xor_sync(0xFFFFFFFFu, ps0, 1);
        ps0 += __shfl_xor_sync(0xFFFFFFFFu, ps0, 2);
        ps1 += __shfl_xor_sync(0xFFFFFFFFu, ps1, 1);
        ps1 += __shfl_xor_sync(0xFFFFFFFFu, ps1, 2);
        l0s = l0s * c0 + ps0;
        l1s = l1s * c1 + ps1;
        #pragma unroll
        for (int tn = 0; tn < 8; tn++) {
            oacc[tn][0] *= c0; oacc[tn][1] *= c0;
            oacc[tn][2] *= c1; oacc[tn][3] *= c1;
        }

        // --- store P (tf32) to warp-private smem, re-fragment for PV ---
        unsigned* Pw = (unsigned*)&P_s[warp * 16 * 68];
        #pragma unroll
        for (int tn = 0; tn < 8; tn++) {
            const int colb = tn * 8 + 2 * lc;
            Pw[lr * 68 + colb]           = f2tf(sacc[tn][0]);
            Pw[lr * 68 + colb + 1]       = f2tf(sacc[tn][1]);
            Pw[(lr + 8) * 68 + colb]     = f2tf(sacc[tn][2]);
            Pw[(lr + 8) * 68 + colb + 1] = f2tf(sacc[tn][3]);
        }
        __syncwarp();

        // --- O += P @ V ---
        #pragma unroll
        for (int ks = 0; ks < 8; ks++) {
            unsigned af[4];
            af[0] = Pw[lr * 68 + ks * 8 + lc];
            af[1] = Pw[(lr + 8) * 68 + ks * 8 + lc];
            af[2] = Pw[lr * 68 + ks * 8 + 4 + lc];
            af[3] = Pw[(lr + 8) * 68 + ks * 8 + 4 + lc];
            #pragma unroll
            for (int tn = 0; tn < 8; tn++) {
                const int cb = tn * 8 + lr;
                unsigned bf[2];
                bf[0] = fbits(V_s[(ks * 8 + lc) * 72 + cb]);
                bf[1] = fbits(V_s[(ks * 8 + 4 + lc) * 72 + cb]);
                mma8(oacc[tn], af, bf);
            }
        }
        __syncthreads();   // protect K_s/V_s before next tile load
    }

    // --- epilogue: O / l ---
    const float inv0 = 1.0f / l0s, inv1 = 1.0f / l1s;
    float* Ob = O + ((size_t)(b * SEQ + l0 + warp * 16)) * D_MODEL + h * HEAD_E;
    #pragma unroll
    for (int tn = 0; tn < 8; tn++) {
        const int col = tn * 8 + 2 * lc;
        float2 v0 = make_float2(oacc[tn][0] * inv0, oacc[tn][1] * inv0);
        float2 v1 = make_float2(oacc[tn][2] * inv1, oacc[tn][3] * inv1);
        *(float2*)&Ob[(size_t)lr * D_MODEL + col]       = v0;
        *(float2*)&Ob[(size_t)(lr + 8) * D_MODEL + col] = v1;
    }
}

// ---------------- residual add + LayerNorm ---------------------------------
__global__ void __launch_bounds__(128)
add_ln_kernel(const float* __restrict__ X, const float* __restrict__ Y,
              const float* __restrict__ g, const float* __restrict__ bta,
              float* __restrict__ Out)
{
    __shared__ float red[8];
    const int row = blockIdx.x;
    const int tid = threadIdx.x;
    const int col = tid * 4;

    float4 xv = *(const float4*)&X[(size_t)row * D_MODEL + col];
    float4 yv = *(const float4*)&Y[(size_t)row * D_MODEL + col];
    float v0 = xv.x + yv.x, v1 = xv.y + yv.y, v2 = xv.z + yv.z, v3 = xv.w + yv.w;

    float sum = v0 + v1 + v2 + v3;
    float sq  = v0 * v0 + v1 * v1 + v2 * v2 + v3 * v3;
    #pragma unroll
    for (int off = 16; off > 0; off >>= 1) {
        sum += __shfl_xor_sync(0xFFFFFFFFu, sum, off);
        sq  += __shfl_xor_sync(0xFFFFFFFFu, sq,  off);
    }
    const int wid  = tid >> 5;
    const int lane = tid & 31;
    if (lane == 0) { red[wid] = sum; red[4 + wid] = sq; }
    __syncthreads();
    sum = red[0] + red[1] + red[2] + red[3];
    sq  = red[4] + red[5] + red[6] + red[7];

    const float mu  = sum * (1.0f / D_MODEL);
    const float var = sq * (1.0f / D_MODEL) - mu * mu;
    const float rst = rsqrtf(var + 1e-5f);

    float4 gv = *(const float4*)&g[col];
    float4 bv = *(const float4*)&bta[col];
    float4 w;
    w.x = (v0 - mu) * rst * gv.x + bv.x;
    w.y = (v1 - mu) * rst * gv.y + bv.y;
    w.z = (v2 - mu) * rst * gv.z + bv.z;
    w.w = (v3 - mu) * rst * gv.w + bv.w;
    *(float4*)&Out[(size_t)row * D_MODEL + col] = w;
}

// ---------------- launcher --------------------------------------------------
extern "C" void kernel_launch(void* const* d_in, const int* in_sizes, int n_in,
                              void* d_out, int out_size)
{
    const float* x   = (const float*)d_in[0];
    const float* Wq  = (const float*)d_in[1];
    const float* bq  = (const float*)d_in[2];
    const float* Wk  = (const float*)d_in[3];
    const float* bk  = (const float*)d_in[4];
    const float* Wv  = (const float*)d_in[5];
    const float* bv  = (const float*)d_in[6];
    const float* Wo  = (const float*)d_in[7];
    const float* bo  = (const float*)d_in[8];
    const float* W1  = (const float*)d_in[9];
    const float* b1  = (const float*)d_in[10];
    const float* W2  = (const float*)d_in[11];
    const float* b2  = (const float*)d_in[12];
    const float* g1  = (const float*)d_in[13];
    const float* be1 = (const float*)d_in[14];
    const float* g2  = (const float*)d_in[15];
    const float* be2 = (const float*)d_in[16];
    float* out = (float*)d_out;

    float *q, *k, *v, *attn, *proj, *x1, *hbuf, *ffn;
    cudaGetSymbolAddress((void**)&q,    g_q);
    cudaGetSymbolAddress((void**)&k,    g_k);
    cudaGetSymbolAddress((void**)&v,    g_v);
    cudaGetSymbolAddress((void**)&attn, g_attn);
    cudaGetSymbolAddress((void**)&proj, g_proj);
    cudaGetSymbolAddress((void**)&x1,   g_x1);
    cudaGetSymbolAddress((void**)&hbuf, g_h);
    cudaGetSymbolAddress((void**)&ffn,  g_ffn);

    const int FLASH_SMEM = (64 * 68 + 64 * 72 + 8 * 16 * 68) * 4;  // 70656
    cudaFuncSetAttribute((const void*)flash_kernel,
                         cudaFuncAttributeMaxDynamicSharedMemorySize, FLASH_SMEM);

    const dim3 gD(D_MODEL / 128, M_ROWS / 128);   // (4, 64)
    const dim3 gF(D_FF   / 128, M_ROWS / 128);    // (16, 64)

    // QKV projections
    mma_gemm<0><<<gD, 256>>>(x, Wq, bq, q, D_MODEL, D_MODEL);
    mma_gemm<0><<<gD, 256>>>(x, Wk, bk, k, D_MODEL, D_MODEL);
    mma_gemm<0><<<gD, 256>>>(x, Wv, bv, v, D_MODEL, D_MODEL);

    // fused flash attention
    flash_kernel<<<dim3(SEQ / 128, BATCH * N_HEADS), 256, FLASH_SMEM>>>(q, k, v, attn);

    // output projection + residual LN1
    mma_gemm<0><<<gD, 256>>>(attn, Wo, bo, proj, D_MODEL, D_MODEL);
    add_ln_kernel<<<M_ROWS, 128>>>(x, proj, g1, be1, x1);

    // FFN (GELU fused) + residual LN2
    mma_gemm<1><<<gF, 256>>>(x1, W1, b1, hbuf, D_MODEL, D_FF);
    mma_gemm<0><<<gD, 256>>>(hbuf, W2, b2, ffn, D_FF, D_MODEL);
    add_ln_kernel<<<M_ROWS, 128>>>(x1, ffn, g2, be2, out);
}